// round 5
// baseline (speedup 1.0000x reference)
#include <cuda_runtime.h>
#include <cstdint>

// ---------------------------------------------------------------------------
// GlideAttention: B=2, QLEN=2048, HID=2048, NH=16, NKV=4, HD=128, BLOCK=4
//   q = hidden @ Wq + bq        (4096 x 2048) @ (2048 x 2048)
//   q = RoPE(q)                 (fused into attention Q-load)
//   attn with glide mask: row i attends kv j iff (j>>2) < (i>>2), plus 4x4 corner
//   out = attn_out @ Wo
// Scratch lives in __device__ globals (no allocation allowed).
// ---------------------------------------------------------------------------

#define Bsz   2
#define QLEN  2048
#define HID   2048
#define NH    16
#define NKV   4
#define HD    128
#define MROWS (Bsz * QLEN)   // 4096

__device__ float g_qtmp[(size_t)MROWS * HID];  // q projection output (pre-RoPE)
__device__ float g_ao  [(size_t)MROWS * HID];  // attention output

// ---------------------------------------------------------------------------
// 128x128x8 SGEMM, 256 threads, 8x8 per-thread tile, register-staged global
// prefetch + DOUBLE-BUFFERED smem (one __syncthreads per K-step).
// C[M,N] = A[M,K] @ B[K,N] (+ bias per column, optional).
// ---------------------------------------------------------------------------
__global__ __launch_bounds__(256) void sgemm128(
    const float* __restrict__ A, const float* __restrict__ B,
    const float* __restrict__ bias, float* __restrict__ C,
    int M, int N, int K)
{
    __shared__ float As[2][8][128];   // [buf][k][m]  (A stored transposed)
    __shared__ float Bs[2][8][128];   // [buf][k][n]

    const int tid = threadIdx.x;
    const int bx = blockIdx.x;     // N tile
    const int by = blockIdx.y;     // M tile
    const int tx = tid & 15;
    const int ty = tid >> 4;

    const int a_r = tid >> 1;             // 0..127
    const int a_c = (tid & 1) << 2;       // 0 or 4
    const int b_r = tid >> 5;             // 0..7
    const int b_c = (tid & 31) << 2;      // 0..124

    const float* Ap = A + (size_t)(by * 128 + a_r) * K + a_c;
    const float* Bp = B + (size_t)b_r * N + bx * 128 + b_c;

    float acc[8][8];
#pragma unroll
    for (int i = 0; i < 8; i++)
#pragma unroll
        for (int j = 0; j < 8; j++) acc[i][j] = 0.0f;

    // ---- preload tile 0 into buffer 0 ----
    {
        float4 av = *(const float4*)Ap;
        float4 bv = *(const float4*)Bp;
        As[0][a_c + 0][a_r] = av.x;
        As[0][a_c + 1][a_r] = av.y;
        As[0][a_c + 2][a_r] = av.z;
        As[0][a_c + 3][a_r] = av.w;
        *(float4*)&Bs[0][b_r][b_c] = bv;
    }
    __syncthreads();

    int cur = 0;
    for (int k0 = 0; k0 < K; k0 += 8) {
        const bool has_next = (k0 + 8 < K);
        float4 av, bv;
        if (has_next) {
            av = *(const float4*)(Ap + k0 + 8);
            bv = *(const float4*)(Bp + (size_t)(k0 + 8) * N);
        }

#pragma unroll
        for (int kk = 0; kk < 8; kk++) {
            float4 a0 = *(const float4*)&As[cur][kk][ty * 8];
            float4 a1 = *(const float4*)&As[cur][kk][ty * 8 + 4];
            float4 b0 = *(const float4*)&Bs[cur][kk][tx * 8];
            float4 b1 = *(const float4*)&Bs[cur][kk][tx * 8 + 4];
            float ar[8] = {a0.x, a0.y, a0.z, a0.w, a1.x, a1.y, a1.z, a1.w};
            float br[8] = {b0.x, b0.y, b0.z, b0.w, b1.x, b1.y, b1.z, b1.w};
#pragma unroll
            for (int i = 0; i < 8; i++)
#pragma unroll
                for (int j = 0; j < 8; j++)
                    acc[i][j] += ar[i] * br[j];
        }

        if (has_next) {
            const int nxt = cur ^ 1;
            As[nxt][a_c + 0][a_r] = av.x;
            As[nxt][a_c + 1][a_r] = av.y;
            As[nxt][a_c + 2][a_r] = av.z;
            As[nxt][a_c + 3][a_r] = av.w;
            *(float4*)&Bs[nxt][b_r][b_c] = bv;
            __syncthreads();   // stores to nxt visible; all reads of cur done
            cur = nxt;
        }
    }

    const int row0 = by * 128 + ty * 8;
    const int col0 = bx * 128 + tx * 8;
    float bb[8];
#pragma unroll
    for (int j = 0; j < 8; j++) bb[j] = bias ? bias[col0 + j] : 0.0f;

#pragma unroll
    for (int i = 0; i < 8; i++) {
        float* Crow = C + (size_t)(row0 + i) * N + col0;
        float4 r0, r1;
        r0.x = acc[i][0] + bb[0]; r0.y = acc[i][1] + bb[1];
        r0.z = acc[i][2] + bb[2]; r0.w = acc[i][3] + bb[3];
        r1.x = acc[i][4] + bb[4]; r1.y = acc[i][5] + bb[5];
        r1.z = acc[i][6] + bb[6]; r1.w = acc[i][7] + bb[7];
        *(float4*)Crow       = r0;
        *(float4*)(Crow + 4) = r1;
    }
}

// ---------------------------------------------------------------------------
// Flash-style glide attention. grid = (32 q-tiles, 16 heads, 2 batch),
// 256 threads. Q tile = 64 rows, KV chunk = 64. Q-load applies RoPE + scale.
// Only the final chunk (kv0 == q0) needs masking.
// smem: Qs[128][64] + Ks[128][64] + Vs[64][128] + Ps[64][65] = 114944 B
// ---------------------------------------------------------------------------
#define ATTN_SMEM_FLOATS (3 * 128 * 64 + 64 * 65)
#define ATTN_SMEM_BYTES  (ATTN_SMEM_FLOATS * 4)

__global__ __launch_bounds__(256) void glide_attn(
    const float* __restrict__ qtmp, const float* __restrict__ kc,
    const float* __restrict__ vc,   const float* __restrict__ cs,
    const float* __restrict__ sn,   float* __restrict__ out)
{
    extern __shared__ float smf[];
    float* Qs = smf;                  // [d][i] : d-major, 128 x 64
    float* Ks = smf + 128 * 64;       // [d][j] : 128 x 64
    float* Vs = smf + 2 * 128 * 64;   // [j][d] : 64 x 128
    float* Ps = smf + 3 * 128 * 64;   // [i][j] : 64 x 65 (padded)

    const int qt = blockIdx.x;
    const int h  = blockIdx.y;
    const int b  = blockIdx.z;
    const int q0 = qt << 6;
    const int kh = h >> 2;            // GQA: groups = 4

    const int tid = threadIdx.x;
    const int tx  = tid & 15;
    const int ty  = tid >> 4;
    const float scale = 0.08838834764831845f;   // 1/sqrt(128)

    // ---- Q load + RoPE + scale, stored d-major ----
    for (int idx = tid; idx < 64 * 16; idx += 256) {
        const int i  = idx >> 4;
        const int d4 = (idx & 15) << 2;          // 0..60
        const int ig = q0 + i;
        const float* qr = qtmp + (size_t)(b * QLEN + ig) * HID + h * HD;
        const float* cr = cs + (size_t)(b * QLEN + ig) * HD;
        const float* sr = sn + (size_t)(b * QLEN + ig) * HD;
        float4 qa = *(const float4*)(qr + d4);
        float4 qb = *(const float4*)(qr + d4 + 64);
        float4 ca = *(const float4*)(cr + d4);
        float4 sa = *(const float4*)(sr + d4);
        float4 cb = *(const float4*)(cr + d4 + 64);
        float4 sb = *(const float4*)(sr + d4 + 64);
        Qs[(d4 + 0) * 64 + i] = (qa.x * ca.x - qb.x * sa.x) * scale;
        Qs[(d4 + 1) * 64 + i] = (qa.y * ca.y - qb.y * sa.y) * scale;
        Qs[(d4 + 2) * 64 + i] = (qa.z * ca.z - qb.z * sa.z) * scale;
        Qs[(d4 + 3) * 64 + i] = (qa.w * ca.w - qb.w * sa.w) * scale;
        Qs[(d4 + 64) * 64 + i] = (qb.x * cb.x + qa.x * sb.x) * scale;
        Qs[(d4 + 65) * 64 + i] = (qb.y * cb.y + qa.y * sb.y) * scale;
        Qs[(d4 + 66) * 64 + i] = (qb.z * cb.z + qa.z * sb.z) * scale;
        Qs[(d4 + 67) * 64 + i] = (qb.w * cb.w + qa.w * sb.w) * scale;
    }

    float m_[4], l_[4], O[4][8];
#pragma unroll
    for (int i = 0; i < 4; i++) {
        m_[i] = -1e30f;
        l_[i] = 0.0f;
#pragma unroll
        for (int j = 0; j < 8; j++) O[i][j] = 0.0f;
    }

    const int nch = q0 >> 6;   // chunks 0..nch; last one (kv0 == q0) is masked
    for (int c = 0; c <= nch; c++) {
        const int kv0 = c << 6;
        __syncthreads();   // previous PV done (and first iter: Q writes done)

        // ---- K (d-major) / V (row-major) load ----
        for (int idx = tid; idx < 64 * 32; idx += 256) {
            const int j  = idx >> 5;
            const int d4 = (idx & 31) << 2;
            const size_t base = ((size_t)(b * QLEN + kv0 + j) * NKV + kh) * HD;
            float4 kv = *(const float4*)(kc + base + d4);
            Ks[(d4 + 0) * 64 + j] = kv.x;
            Ks[(d4 + 1) * 64 + j] = kv.y;
            Ks[(d4 + 2) * 64 + j] = kv.z;
            Ks[(d4 + 3) * 64 + j] = kv.w;
            *(float4*)&Vs[j * 128 + d4] = *(const float4*)(vc + base + d4);
        }
        __syncthreads();

        // ---- scores: 4x4 per thread ----
        float s[4][4];
#pragma unroll
        for (int i = 0; i < 4; i++)
#pragma unroll
            for (int j = 0; j < 4; j++) s[i][j] = 0.0f;

#pragma unroll 4
        for (int d = 0; d < 128; d++) {
            float4 q4 = *(const float4*)&Qs[d * 64 + ty * 4];
            float4 k4 = *(const float4*)&Ks[d * 64 + tx * 4];
            s[0][0] += q4.x * k4.x; s[0][1] += q4.x * k4.y; s[0][2] += q4.x * k4.z; s[0][3] += q4.x * k4.w;
            s[1][0] += q4.y * k4.x; s[1][1] += q4.y * k4.y; s[1][2] += q4.y * k4.z; s[1][3] += q4.y * k4.w;
            s[2][0] += q4.z * k4.x; s[2][1] += q4.z * k4.y; s[2][2] += q4.z * k4.z; s[2][3] += q4.z * k4.w;
            s[3][0] += q4.w * k4.x; s[3][1] += q4.w * k4.y; s[3][2] += q4.w * k4.z; s[3][3] += q4.w * k4.w;
        }

        if (c == nch) {   // only the last chunk is partially masked
#pragma unroll
            for (int i = 0; i < 4; i++) {
                const int ib = (q0 + ty * 4 + i) >> 2;
#pragma unroll
                for (int j = 0; j < 4; j++) {
                    const int jb = (kv0 + tx * 4 + j) >> 2;
                    const bool ok = (jb < ib) || (ib == 0 && jb == 0);
                    if (!ok) s[i][j] = -1e30f;
                }
            }
        }

        // ---- online softmax (row reduce across the 16 tx lanes) ----
        float rmax[4];
#pragma unroll
        for (int i = 0; i < 4; i++)
            rmax[i] = fmaxf(fmaxf(s[i][0], s[i][1]), fmaxf(s[i][2], s[i][3]));
#pragma unroll
        for (int off = 8; off >= 1; off >>= 1)
#pragma unroll
            for (int i = 0; i < 4; i++)
                rmax[i] = fmaxf(rmax[i], __shfl_xor_sync(0xffffffffu, rmax[i], off));

        float al[4];
#pragma unroll
        for (int i = 0; i < 4; i++) {
            float nm = fmaxf(m_[i], rmax[i]);
            al[i] = __expf(m_[i] - nm);
            m_[i] = nm;
        }

        float rsum[4];
#pragma unroll
        for (int i = 0; i < 4; i++) {
            rsum[i] = 0.0f;
#pragma unroll
            for (int j = 0; j < 4; j++) {
                float p = __expf(s[i][j] - m_[i]);
                Ps[(ty * 4 + i) * 65 + tx * 4 + j] = p;
                rsum[i] += p;
            }
        }
#pragma unroll
        for (int off = 8; off >= 1; off >>= 1)
#pragma unroll
            for (int i = 0; i < 4; i++)
                rsum[i] += __shfl_xor_sync(0xffffffffu, rsum[i], off);

#pragma unroll
        for (int i = 0; i < 4; i++) {
            l_[i] = l_[i] * al[i] + rsum[i];
#pragma unroll
            for (int j = 0; j < 8; j++) O[i][j] *= al[i];
        }
        __syncthreads();   // Ps visible to all

        // ---- PV: O[4 rows][8 cols] += P[64] @ V[64][128] slice ----
#pragma unroll 2
        for (int j = 0; j < 64; j++) {
            float p0 = Ps[(ty * 4 + 0) * 65 + j];
            float p1 = Ps[(ty * 4 + 1) * 65 + j];
            float p2 = Ps[(ty * 4 + 2) * 65 + j];
            float p3 = Ps[(ty * 4 + 3) * 65 + j];
            float4 v0 = *(const float4*)&Vs[j * 128 + tx * 8];
            float4 v1 = *(const float4*)&Vs[j * 128 + tx * 8 + 4];
            O[0][0] += p0 * v0.x; O[0][1] += p0 * v0.y; O[0][2] += p0 * v0.z; O[0][3] += p0 * v0.w;
            O[0][4] += p0 * v1.x; O[0][5] += p0 * v1.y; O[0][6] += p0 * v1.z; O[0][7] += p0 * v1.w;
            O[1][0] += p1 * v0.x; O[1][1] += p1 * v0.y; O[1][2] += p1 * v0.z; O[1][3] += p1 * v0.w;
            O[1][4] += p1 * v1.x; O[1][5] += p1 * v1.y; O[1][6] += p1 * v1.z; O[1][7] += p1 * v1.w;
            O[2][0] += p2 * v0.x; O[2][1] += p2 * v0.y; O[2][2] += p2 * v0.z; O[2][3] += p2 * v0.w;
            O[2][4] += p2 * v1.x; O[2][5] += p2 * v1.y; O[2][6] += p2 * v1.z; O[2][7] += p2 * v1.w;
            O[3][0] += p3 * v0.x; O[3][1] += p3 * v0.y; O[3][2] += p3 * v0.z; O[3][3] += p3 * v0.w;
            O[3][4] += p3 * v1.x; O[3][5] += p3 * v1.y; O[3][6] += p3 * v1.z; O[3][7] += p3 * v1.w;
        }
    }

    // ---- epilogue: normalize + store to (b, i, h*128+d) ----
#pragma unroll
    for (int i = 0; i < 4; i++) {
        const float inv = 1.0f / l_[i];
        const int row = b * QLEN + q0 + ty * 4 + i;
        float* op = out + (size_t)row * HID + h * HD + tx * 8;
        float4 o0, o1;
        o0.x = O[i][0] * inv; o0.y = O[i][1] * inv; o0.z = O[i][2] * inv; o0.w = O[i][3] * inv;
        o1.x = O[i][4] * inv; o1.y = O[i][5] * inv; o1.z = O[i][6] * inv; o1.w = O[i][7] * inv;
        *(float4*)op       = o0;
        *(float4*)(op + 4) = o1;
    }
}

// ---------------------------------------------------------------------------
extern "C" void kernel_launch(void* const* d_in, const int* in_sizes, int n_in,
                              void* d_out, int out_size)
{
    const float* hidden = (const float*)d_in[0];
    const float* kc     = (const float*)d_in[1];
    const float* vc     = (const float*)d_in[2];
    const float* cs     = (const float*)d_in[3];
    const float* sn     = (const float*)d_in[4];
    const float* Wq     = (const float*)d_in[5];
    const float* bq     = (const float*)d_in[6];
    const float* Wo     = (const float*)d_in[7];
    float* out = (float*)d_out;

    float *qtmp, *ao;
    cudaGetSymbolAddress((void**)&qtmp, g_qtmp);
    cudaGetSymbolAddress((void**)&ao,   g_ao);

    cudaFuncSetAttribute(glide_attn, cudaFuncAttributeMaxDynamicSharedMemorySize,
                         ATTN_SMEM_BYTES);

    // 1) Q projection: (4096 x 2048) @ Wq + bq
    sgemm128<<<dim3(HID / 128, MROWS / 128), 256>>>(hidden, Wq, bq, qtmp,
                                                    MROWS, HID, HID);
    // 2) RoPE + glide attention
    glide_attn<<<dim3(QLEN / 64, NH, Bsz), 256, ATTN_SMEM_BYTES>>>(qtmp, kc, vc,
                                                                   cs, sn, ao);
    // 3) O projection: (4096 x 2048) @ Wo
    sgemm128<<<dim3(HID / 128, MROWS / 128), 256>>>(ao, Wo, nullptr, out,
                                                    MROWS, HID, HID);
}

// round 10
// speedup vs baseline: 1.5288x; 1.5288x over previous
#include <cuda_runtime.h>
#include <cstdint>

// ---------------------------------------------------------------------------
// GlideAttention: B=2, QLEN=2048, HID=2048, NH=16, NKV=4, HD=128, BLOCK=4
//   q = hidden @ Wq + bq        [TF32 tensor]
//   q = RoPE(q)                 (fused into attention Q-load)
//   attn glide mask: row i attends kv j iff (j>>2) < (i>>2), plus 4x4 corner
//     QK^T on tensor cores (TF32), softmax + PV unchanged (fp32)
//   out = attn_out @ Wo         [TF32 tensor]
// ---------------------------------------------------------------------------

#define Bsz   2
#define QLEN  2048
#define HID   2048
#define NH    16
#define NKV   4
#define HD    128
#define MROWS (Bsz * QLEN)   // 4096

__device__ float g_qtmp[(size_t)MROWS * HID];  // q projection output (pre-RoPE)
__device__ float g_ao  [(size_t)MROWS * HID];  // attention output

// ---------------------------------------------------------------------------
// Shared TF32 mma primitive: m16n8k8.row.col, fp32 accumulate.
// A frag (row-major M x K): a0=(lg,lc) a1=(lg+8,lc) a2=(lg,lc+4) a3=(lg+8,lc+4)
// B frag (col-major K x N): b0=(lc,lg) b1=(lc+4,lg)
// C frag: c0,c1=(lg, 2lc/2lc+1), c2,c3=(lg+8, ...)
// ---------------------------------------------------------------------------
__device__ __forceinline__ float ftf32(float x) {
    asm("cvt.rna.tf32.f32 %0, %0;" : "+f"(x));
    return x;
}

__device__ __forceinline__ void mma_tf32(
    float& c0, float& c1, float& c2, float& c3,
    uint32_t a0, uint32_t a1, uint32_t a2, uint32_t a3,
    uint32_t b0, uint32_t b1)
{
    asm volatile(
        "mma.sync.aligned.m16n8k8.row.col.f32.tf32.tf32.f32 "
        "{%0,%1,%2,%3}, {%4,%5,%6,%7}, {%8,%9}, {%0,%1,%2,%3};"
        : "+f"(c0), "+f"(c1), "+f"(c2), "+f"(c3)
        : "r"(a0), "r"(a1), "r"(a2), "r"(a3), "r"(b0), "r"(b1));
}

// ---------------------------------------------------------------------------
// TF32 tensor-core GEMM: C[M,N] = A[M,K] @ B[K,N] (+ optional bias per col).
// 128x128 CTA tile, 256 threads = 8 warps (4 M x 2 N), warp tile 32x64.
// K-step 16, double-buffered. smem stride 136 (== 8 mod 32): fragment LDS
// bank = 8*lc + lg -> conflict-free.
// ---------------------------------------------------------------------------
#define GPAD 8
#define GSTR (128 + GPAD)

__global__ __launch_bounds__(256) void gemm_tf32(
    const float* __restrict__ A, const float* __restrict__ B,
    const float* __restrict__ bias, float* __restrict__ C,
    int M, int N, int K)
{
    __shared__ float As[2][16][GSTR];   // [buf][k][m]  (A transposed on store)
    __shared__ float Bs[2][16][GSTR];   // [buf][k][n]

    const int tid  = threadIdx.x;
    const int lane = tid & 31;
    const int warp = tid >> 5;
    const int wm   = warp >> 1;          // 0..3  (M)
    const int wn   = warp & 1;           // 0..1  (N)
    const int bx   = blockIdx.x;         // N tile
    const int by   = blockIdx.y;         // M tile

    const int a_r  = tid >> 1;           // 0..127 (M row)
    const int a_k8 = (tid & 1) * 8;      // k offset 0 or 8
    const int b_k  = tid >> 4;           // 0..15  (K row)
    const int b_n8 = (tid & 15) * 8;     // n offset 0..120

    const float* Ap = A + (size_t)(by * 128 + a_r) * K + a_k8;
    const float* Bp = B + (size_t)b_k * N + bx * 128 + b_n8;

    float c[2][8][4];
#pragma unroll
    for (int mt = 0; mt < 2; mt++)
#pragma unroll
        for (int nt = 0; nt < 8; nt++)
#pragma unroll
            for (int r = 0; r < 4; r++) c[mt][nt][r] = 0.0f;

    // ---- preload tile 0 into buffer 0 ----
    {
        float4 a0 = *(const float4*)(Ap);
        float4 a1 = *(const float4*)(Ap + 4);
        As[0][a_k8 + 0][a_r] = ftf32(a0.x);
        As[0][a_k8 + 1][a_r] = ftf32(a0.y);
        As[0][a_k8 + 2][a_r] = ftf32(a0.z);
        As[0][a_k8 + 3][a_r] = ftf32(a0.w);
        As[0][a_k8 + 4][a_r] = ftf32(a1.x);
        As[0][a_k8 + 5][a_r] = ftf32(a1.y);
        As[0][a_k8 + 6][a_r] = ftf32(a1.z);
        As[0][a_k8 + 7][a_r] = ftf32(a1.w);
        float4 b0 = *(const float4*)(Bp);
        float4 b1 = *(const float4*)(Bp + 4);
        Bs[0][b_k][b_n8 + 0] = ftf32(b0.x);
        Bs[0][b_k][b_n8 + 1] = ftf32(b0.y);
        Bs[0][b_k][b_n8 + 2] = ftf32(b0.z);
        Bs[0][b_k][b_n8 + 3] = ftf32(b0.w);
        Bs[0][b_k][b_n8 + 4] = ftf32(b1.x);
        Bs[0][b_k][b_n8 + 5] = ftf32(b1.y);
        Bs[0][b_k][b_n8 + 6] = ftf32(b1.z);
        Bs[0][b_k][b_n8 + 7] = ftf32(b1.w);
    }
    __syncthreads();

    const int lg = lane >> 2;   // 0..7
    const int lc = lane & 3;    // 0..3

    int cur = 0;
    for (int k0 = 0; k0 < K; k0 += 16) {
        const bool has_next = (k0 + 16 < K);
        float4 pa0, pa1, pb0, pb1;
        if (has_next) {
            pa0 = *(const float4*)(Ap + k0 + 16);
            pa1 = *(const float4*)(Ap + k0 + 20);
            pb0 = *(const float4*)(Bp + (size_t)(k0 + 16) * N);
            pb1 = *(const float4*)(Bp + (size_t)(k0 + 16) * N + 4);
        }

#pragma unroll
        for (int kk = 0; kk < 16; kk += 8) {
            uint32_t af[2][4];
#pragma unroll
            for (int mt = 0; mt < 2; mt++) {
                const int m = wm * 32 + mt * 16 + lg;
                af[mt][0] = __float_as_uint(As[cur][kk + lc    ][m    ]);
                af[mt][1] = __float_as_uint(As[cur][kk + lc    ][m + 8]);
                af[mt][2] = __float_as_uint(As[cur][kk + lc + 4][m    ]);
                af[mt][3] = __float_as_uint(As[cur][kk + lc + 4][m + 8]);
            }
#pragma unroll
            for (int nt = 0; nt < 8; nt++) {
                const int n = wn * 64 + nt * 8 + lg;
                uint32_t b0 = __float_as_uint(Bs[cur][kk + lc    ][n]);
                uint32_t b1 = __float_as_uint(Bs[cur][kk + lc + 4][n]);
#pragma unroll
                for (int mt = 0; mt < 2; mt++)
                    mma_tf32(c[mt][nt][0], c[mt][nt][1], c[mt][nt][2], c[mt][nt][3],
                             af[mt][0], af[mt][1], af[mt][2], af[mt][3], b0, b1);
            }
        }

        if (has_next) {
            const int nxt = cur ^ 1;
            As[nxt][a_k8 + 0][a_r] = ftf32(pa0.x);
            As[nxt][a_k8 + 1][a_r] = ftf32(pa0.y);
            As[nxt][a_k8 + 2][a_r] = ftf32(pa0.z);
            As[nxt][a_k8 + 3][a_r] = ftf32(pa0.w);
            As[nxt][a_k8 + 4][a_r] = ftf32(pa1.x);
            As[nxt][a_k8 + 5][a_r] = ftf32(pa1.y);
            As[nxt][a_k8 + 6][a_r] = ftf32(pa1.z);
            As[nxt][a_k8 + 7][a_r] = ftf32(pa1.w);
            Bs[nxt][b_k][b_n8 + 0] = ftf32(pb0.x);
            Bs[nxt][b_k][b_n8 + 1] = ftf32(pb0.y);
            Bs[nxt][b_k][b_n8 + 2] = ftf32(pb0.z);
            Bs[nxt][b_k][b_n8 + 3] = ftf32(pb0.w);
            Bs[nxt][b_k][b_n8 + 4] = ftf32(pb1.x);
            Bs[nxt][b_k][b_n8 + 5] = ftf32(pb1.y);
            Bs[nxt][b_k][b_n8 + 6] = ftf32(pb1.z);
            Bs[nxt][b_k][b_n8 + 7] = ftf32(pb1.w);
            __syncthreads();
            cur = nxt;
        }
    }

    // ---- epilogue ----
#pragma unroll
    for (int mt = 0; mt < 2; mt++) {
        const int r0 = by * 128 + wm * 32 + mt * 16 + lg;
#pragma unroll
        for (int nt = 0; nt < 8; nt++) {
            const int cn = bx * 128 + wn * 64 + nt * 8 + lc * 2;
            float bb0 = bias ? bias[cn]     : 0.0f;
            float bb1 = bias ? bias[cn + 1] : 0.0f;
            C[(size_t)r0 * N + cn]           = c[mt][nt][0] + bb0;
            C[(size_t)r0 * N + cn + 1]       = c[mt][nt][1] + bb1;
            C[(size_t)(r0 + 8) * N + cn]     = c[mt][nt][2] + bb0;
            C[(size_t)(r0 + 8) * N + cn + 1] = c[mt][nt][3] + bb1;
        }
    }
}

// ---------------------------------------------------------------------------
// Flash-style glide attention. grid = (32 q-tiles, 16 heads, 2 batch),
// 256 threads. Q tile = 64 rows, KV chunk = 64. RoPE fused into Q load.
// QK^T on tensor cores: 8 warps (4 M x 2 N), warp tile 16x32, raw scores
// dumped to Ps smem; mask/online-softmax/PV unchanged (read s from Ps).
// Qs/Ks stride 72 (== 8 mod 32): fragment LDS conflict-free.
// Only the final chunk (kv0 == q0) needs masking.
// ---------------------------------------------------------------------------
#define QSTR 72
#define ATTN_SMEM_FLOATS (2 * 128 * QSTR + 64 * 128 + 64 * 65)
#define ATTN_SMEM_BYTES  (ATTN_SMEM_FLOATS * 4)

__global__ __launch_bounds__(256) void glide_attn(
    const float* __restrict__ qtmp, const float* __restrict__ kc,
    const float* __restrict__ vc,   const float* __restrict__ cs,
    const float* __restrict__ sn,   float* __restrict__ out)
{
    extern __shared__ float smf[];
    float* Qs = smf;                         // [d][i] : 128 x QSTR (tf32 bits)
    float* Ks = smf + 128 * QSTR;            // [d][j] : 128 x QSTR (tf32 bits)
    float* Vs = smf + 2 * 128 * QSTR;        // [j][d] : 64 x 128
    float* Ps = smf + 2 * 128 * QSTR + 64 * 128;  // [i][j] : 64 x 65

    const int qt = blockIdx.x;
    const int h  = blockIdx.y;
    const int b  = blockIdx.z;
    const int q0 = qt << 6;
    const int kh = h >> 2;            // GQA: groups = 4

    const int tid  = threadIdx.x;
    const int tx   = tid & 15;
    const int ty   = tid >> 4;
    const int lane = tid & 31;
    const int warp = tid >> 5;
    const int wm   = warp >> 1;       // 0..3 (M subtile of 16)
    const int wn   = warp & 1;        // 0..1 (N half of 32)
    const int lg   = lane >> 2;       // 0..7
    const int lc   = lane & 3;        // 0..3
    const float scale = 0.08838834764831845f;   // 1/sqrt(128)

    // ---- Q load + RoPE + scale (tf32-rounded), stored d-major ----
    for (int idx = tid; idx < 64 * 16; idx += 256) {
        const int i  = idx >> 4;
        const int d4 = (idx & 15) << 2;          // 0..60
        const int ig = q0 + i;
        const float* qr = qtmp + (size_t)(b * QLEN + ig) * HID + h * HD;
        const float* cr = cs + (size_t)(b * QLEN + ig) * HD;
        const float* sr = sn + (size_t)(b * QLEN + ig) * HD;
        float4 qa = *(const float4*)(qr + d4);
        float4 qb = *(const float4*)(qr + d4 + 64);
        float4 ca = *(const float4*)(cr + d4);
        float4 sa = *(const float4*)(sr + d4);
        float4 cb = *(const float4*)(cr + d4 + 64);
        float4 sb = *(const float4*)(sr + d4 + 64);
        Qs[(d4 + 0) * QSTR + i] = ftf32((qa.x * ca.x - qb.x * sa.x) * scale);
        Qs[(d4 + 1) * QSTR + i] = ftf32((qa.y * ca.y - qb.y * sa.y) * scale);
        Qs[(d4 + 2) * QSTR + i] = ftf32((qa.z * ca.z - qb.z * sa.z) * scale);
        Qs[(d4 + 3) * QSTR + i] = ftf32((qa.w * ca.w - qb.w * sa.w) * scale);
        Qs[(d4 + 64) * QSTR + i] = ftf32((qb.x * cb.x + qa.x * sb.x) * scale);
        Qs[(d4 + 65) * QSTR + i] = ftf32((qb.y * cb.y + qa.y * sb.y) * scale);
        Qs[(d4 + 66) * QSTR + i] = ftf32((qb.z * cb.z + qa.z * sb.z) * scale);
        Qs[(d4 + 67) * QSTR + i] = ftf32((qb.w * cb.w + qa.w * sb.w) * scale);
    }

    float m_[4], l_[4], O[4][8];
#pragma unroll
    for (int i = 0; i < 4; i++) {
        m_[i] = -1e30f;
        l_[i] = 0.0f;
#pragma unroll
        for (int j = 0; j < 8; j++) O[i][j] = 0.0f;
    }

    const int nch = q0 >> 6;   // chunks 0..nch; last one (kv0 == q0) is masked
    for (int c = 0; c <= nch; c++) {
        const int kv0 = c << 6;
        __syncthreads();   // prev PV (Ps/Vs reads) done; first iter: Q writes done

        // ---- K (d-major, tf32) / V (row-major, fp32) load ----
        for (int idx = tid; idx < 64 * 32; idx += 256) {
            const int j  = idx >> 5;
            const int d4 = (idx & 31) << 2;
            const size_t base = ((size_t)(b * QLEN + kv0 + j) * NKV + kh) * HD;
            float4 kv = *(const float4*)(kc + base + d4);
            Ks[(d4 + 0) * QSTR + j] = ftf32(kv.x);
            Ks[(d4 + 1) * QSTR + j] = ftf32(kv.y);
            Ks[(d4 + 2) * QSTR + j] = ftf32(kv.z);
            Ks[(d4 + 3) * QSTR + j] = ftf32(kv.w);
            *(float4*)&Vs[j * 128 + d4] = *(const float4*)(vc + base + d4);
        }
        __syncthreads();

        // ---- scores via tensor cores: S(64x64) = Q(64x128) @ K^T ----
        // warp tile: rows wm*16 + {lg, lg+8}; cols wn*32 + nt*8 + 2lc + {0,1}
        float sc[4][4];
#pragma unroll
        for (int nt = 0; nt < 4; nt++)
#pragma unroll
            for (int r = 0; r < 4; r++) sc[nt][r] = 0.0f;

#pragma unroll
        for (int kk = 0; kk < 128; kk += 8) {
            const int m = wm * 16 + lg;
            uint32_t a0 = __float_as_uint(Qs[(kk + lc    ) * QSTR + m    ]);
            uint32_t a1 = __float_as_uint(Qs[(kk + lc    ) * QSTR + m + 8]);
            uint32_t a2 = __float_as_uint(Qs[(kk + lc + 4) * QSTR + m    ]);
            uint32_t a3 = __float_as_uint(Qs[(kk + lc + 4) * QSTR + m + 8]);
#pragma unroll
            for (int nt = 0; nt < 4; nt++) {
                const int n = wn * 32 + nt * 8 + lg;
                uint32_t b0 = __float_as_uint(Ks[(kk + lc    ) * QSTR + n]);
                uint32_t b1 = __float_as_uint(Ks[(kk + lc + 4) * QSTR + n]);
                mma_tf32(sc[nt][0], sc[nt][1], sc[nt][2], sc[nt][3],
                         a0, a1, a2, a3, b0, b1);
            }
        }

        // dump raw scores to Ps
#pragma unroll
        for (int nt = 0; nt < 4; nt++) {
            const int row = wm * 16 + lg;
            const int col = wn * 32 + nt * 8 + lc * 2;
            Ps[row * 65 + col]           = sc[nt][0];
            Ps[row * 65 + col + 1]       = sc[nt][1];
            Ps[(row + 8) * 65 + col]     = sc[nt][2];
            Ps[(row + 8) * 65 + col + 1] = sc[nt][3];
        }
        __syncthreads();   // scores visible

        // ---- read back this thread's 4x4 block (old mapping) ----
        float s[4][4];
#pragma unroll
        for (int i = 0; i < 4; i++)
#pragma unroll
            for (int j = 0; j < 4; j++)
                s[i][j] = Ps[(ty * 4 + i) * 65 + tx * 4 + j];

        if (c == nch) {   // only the last chunk is partially masked
#pragma unroll
            for (int i = 0; i < 4; i++) {
                const int ib = (q0 + ty * 4 + i) >> 2;
#pragma unroll
                for (int j = 0; j < 4; j++) {
                    const int jb = (kv0 + tx * 4 + j) >> 2;
                    const bool ok = (jb < ib) || (ib == 0 && jb == 0);
                    if (!ok) s[i][j] = -1e30f;
                }
            }
        }

        // ---- online softmax (row reduce across the 16 tx lanes) ----
        float rmax[4];
#pragma unroll
        for (int i = 0; i < 4; i++)
            rmax[i] = fmaxf(fmaxf(s[i][0], s[i][1]), fmaxf(s[i][2], s[i][3]));
#pragma unroll
        for (int off = 8; off >= 1; off >>= 1)
#pragma unroll
            for (int i = 0; i < 4; i++)
                rmax[i] = fmaxf(rmax[i], __shfl_xor_sync(0xffffffffu, rmax[i], off));

        float al[4];
#pragma unroll
        for (int i = 0; i < 4; i++) {
            float nm = fmaxf(m_[i], rmax[i]);
            al[i] = __expf(m_[i] - nm);
            m_[i] = nm;
        }

        float rsum[4];
#pragma unroll
        for (int i = 0; i < 4; i++) {
            rsum[i] = 0.0f;
#pragma unroll
            for (int j = 0; j < 4; j++) {
                float p = __expf(s[i][j] - m_[i]);
                Ps[(ty * 4 + i) * 65 + tx * 4 + j] = p;   // overwrite own cells
                rsum[i] += p;
            }
        }
#pragma unroll
        for (int off = 8; off >= 1; off >>= 1)
#pragma unroll
            for (int i = 0; i < 4; i++)
                rsum[i] += __shfl_xor_sync(0xffffffffu, rsum[i], off);

#pragma unroll
        for (int i = 0; i < 4; i++) {
            l_[i] = l_[i] * al[i] + rsum[i];
#pragma unroll
            for (int j = 0; j < 8; j++) O[i][j] *= al[i];
        }
        __syncthreads();   // Ps probabilities visible to all

        // ---- PV: O[4 rows][8 cols] += P[64] @ V[64][128] slice ----
#pragma unroll 2
        for (int j = 0; j < 64; j++) {
            float p0 = Ps[(ty * 4 + 0) * 65 + j];
            float p1 = Ps[(ty * 4 + 1) * 65 + j];
            float p2 = Ps[(ty * 4 + 2) * 65 + j];
            float p3 = Ps[(ty * 4 + 3) * 65 + j];
            float4 v0 = *(const float4*)&Vs[j * 128 + tx * 8];
            float4 v1 = *(const float4*)&Vs[j * 128 + tx * 8 + 4];
            O[0][0] += p0 * v0.x; O[0][1] += p0 * v0.y; O[0][2] += p0 * v0.z; O[0][3] += p0 * v0.w;
            O[0][4] += p0 * v1.x; O[0][5] += p0 * v1.y; O[0][6] += p0 * v1.z; O[0][7] += p0 * v1.w;
            O[1][0] += p1 * v0.x; O[1][1] += p1 * v0.y; O[1][2] += p1 * v0.z; O[1][3] += p1 * v0.w;
            O[1][4] += p1 * v1.x; O[1][5] += p1 * v1.y; O[1][6] += p1 * v1.z; O[1][7] += p1 * v1.w;
            O[2][0] += p2 * v0.x; O[2][1] += p2 * v0.y; O[2][2] += p2 * v0.z; O[2][3] += p2 * v0.w;
            O[2][4] += p2 * v1.x; O[2][5] += p2 * v1.y; O[2][6] += p2 * v1.z; O[2][7] += p2 * v1.w;
            O[3][0] += p3 * v0.x; O[3][1] += p3 * v0.y; O[3][2] += p3 * v0.z; O[3][3] += p3 * v0.w;
            O[3][4] += p3 * v1.x; O[3][5] += p3 * v1.y; O[3][6] += p3 * v1.z; O[3][7] += p3 * v1.w;
        }
    }

    // ---- epilogue: normalize + store to (b, i, h*128+d) ----
#pragma unroll
    for (int i = 0; i < 4; i++) {
        const float inv = 1.0f / l_[i];
        const int row = b * QLEN + q0 + ty * 4 + i;
        float* op = out + (size_t)row * HID + h * HD + tx * 8;
        float4 o0, o1;
        o0.x = O[i][0] * inv; o0.y = O[i][1] * inv; o0.z = O[i][2] * inv; o0.w = O[i][3] * inv;
        o1.x = O[i][4] * inv; o1.y = O[i][5] * inv; o1.z = O[i][6] * inv; o1.w = O[i][7] * inv;
        *(float4*)op       = o0;
        *(float4*)(op + 4) = o1;
    }
}

// ---------------------------------------------------------------------------
extern "C" void kernel_launch(void* const* d_in, const int* in_sizes, int n_in,
                              void* d_out, int out_size)
{
    const float* hidden = (const float*)d_in[0];
    const float* kc     = (const float*)d_in[1];
    const float* vc     = (const float*)d_in[2];
    const float* cs     = (const float*)d_in[3];
    const float* sn     = (const float*)d_in[4];
    const float* Wq     = (const float*)d_in[5];
    const float* bq     = (const float*)d_in[6];
    const float* Wo     = (const float*)d_in[7];
    float* out = (float*)d_out;

    float *qtmp, *ao;
    cudaGetSymbolAddress((void**)&qtmp, g_qtmp);
    cudaGetSymbolAddress((void**)&ao,   g_ao);

    cudaFuncSetAttribute(glide_attn, cudaFuncAttributeMaxDynamicSharedMemorySize,
                         ATTN_SMEM_BYTES);

    // 1) Q projection: (4096 x 2048) @ Wq + bq   [TF32 tensor cores]
    gemm_tf32<<<dim3(HID / 128, MROWS / 128), 256>>>(hidden, Wq, bq, qtmp,
                                                     MROWS, HID, HID);
    // 2) RoPE + glide attention (QK^T on tensor cores)
    glide_attn<<<dim3(QLEN / 64, NH, Bsz), 256, ATTN_SMEM_BYTES>>>(qtmp, kc, vc,
                                                                   cs, sn, ao);
    // 3) O projection: (4096 x 2048) @ Wo        [TF32 tensor cores]
    gemm_tf32<<<dim3(HID / 128, MROWS / 128), 256>>>(ao, Wo, nullptr, out,
                                                     MROWS, HID, HID);
}